// round 15
// baseline (speedup 1.0000x reference)
#include <cuda_runtime.h>
#include <cuda_bf16.h>
#include <math.h>
#include <stdint.h>

#define N_NODES 50000
#define M_PAD   50048       // 391 * 128
#define N_EDGES 800000
#define E_TOT   850000
#define N_GRAPHS 64
#define IN_DIM 773
#define KP1 800             // 773 padded to 25 chunks of 32
#define HID 256
#define OUT_DIM 128
#define HEADS 4
#define NEG_SLOPE 0.2f

// ---------------- scratch -----------------------------------------------
__device__ __align__(16) float g_HT1[(size_t)M_PAD * HID];
__device__ __align__(16) float g_HT2[(size_t)M_PAD * OUT_DIM];
__device__ __align__(16) __nv_bfloat16 g_Ahi [(size_t)M_PAD * KP1];
__device__ __align__(16) __nv_bfloat16 g_Alo [(size_t)M_PAD * KP1];
__device__ __align__(16) __nv_bfloat16 g_A2hi[(size_t)M_PAD * HID];
__device__ __align__(16) __nv_bfloat16 g_A2lo[(size_t)M_PAD * HID];
__device__ __align__(16) __nv_bfloat16 g_Bhi[(size_t)HID * KP1];
__device__ __align__(16) __nv_bfloat16 g_Blo[(size_t)HID * KP1];
__device__ __align__(16) float g_AS [N_NODES * HEADS];
__device__ __align__(16) float g_AD [N_NODES * HEADS];
__device__ __align__(16) float g_POOL[N_GRAPHS * OUT_DIM];
__device__ __align__(16) float g_CNT [N_GRAPHS];
// CSR
__device__ int g_deg[N_NODES];
__device__ int g_pos[N_NODES];
__device__ int g_off[N_NODES + 1];
__device__ int g_csr_src[E_TOT];

// ---------------- helpers ----------------------------------------------
__device__ __forceinline__ uint32_t smem_to_u32(const void* p) {
    uint32_t a;
    asm("{ .reg .u64 t; cvta.to.shared.u64 t, %1; cvt.u32.u64 %0, t; }" : "=r"(a) : "l"(p));
    return a;
}
__device__ __forceinline__ void cp_async16(uint32_t s, const void* g) {
    asm volatile("cp.async.cg.shared.global [%0], [%1], 16;" :: "r"(s), "l"(g));
}
#define CP_COMMIT() asm volatile("cp.async.commit_group;" ::: "memory")
#define CP_WAIT1()  asm volatile("cp.async.wait_group 1;" ::: "memory")
#define CP_WAIT0()  asm volatile("cp.async.wait_group 0;" ::: "memory")

__device__ __forceinline__ void mma16816(float* d, const uint32_t* a, const uint32_t* b) {
    asm volatile("mma.sync.aligned.m16n8k16.row.col.f32.bf16.bf16.f32 "
        "{%0,%1,%2,%3}, {%4,%5,%6,%7}, {%8,%9}, {%0,%1,%2,%3};"
        : "+f"(d[0]), "+f"(d[1]), "+f"(d[2]), "+f"(d[3])
        : "r"(a[0]), "r"(a[1]), "r"(a[2]), "r"(a[3]), "r"(b[0]), "r"(b[1]));
}
__device__ __forceinline__ void ldm_x4(uint32_t* r, uint32_t saddr) {
    asm volatile("ldmatrix.sync.aligned.m8n8.x4.shared.b16 {%0,%1,%2,%3}, [%4];"
        : "=r"(r[0]), "=r"(r[1]), "=r"(r[2]), "=r"(r[3]) : "r"(saddr));
}
__device__ __forceinline__ void red_add_v4(float* p, float a, float b, float c, float d) {
    asm volatile("red.global.add.v4.f32 [%0], {%1, %2, %3, %4};"
                 :: "l"(p), "f"(a), "f"(b), "f"(c), "f"(d) : "memory");
}
__device__ __forceinline__ float lrelu(float v) { return v >= 0.f ? v : NEG_SLOPE * v; }

// XOR swizzle (rows x 64B): byte ^= bits[9:7] -> bits[6:4]
__device__ __forceinline__ uint32_t sw64(uint32_t b) {
    return b ^ (((b >> 7) & 7u) << 4);
}

__device__ __forceinline__ void split2(__nv_bfloat16* hi, __nv_bfloat16* lo,
                                       size_t off, float v0, float v1)
{
    __nv_bfloat16 h0 = __float2bfloat16(v0), h1 = __float2bfloat16(v1);
    __nv_bfloat16 l0 = __float2bfloat16(v0 - __bfloat162float(h0));
    __nv_bfloat16 l1 = __float2bfloat16(v1 - __bfloat162float(h1));
    __nv_bfloat162 vh; vh.x = h0; vh.y = h1;
    __nv_bfloat162 vl; vl.x = l0; vl.y = l1;
    *(__nv_bfloat162*)(hi + off) = vh;
    *(__nv_bfloat162*)(lo + off) = vl;
}

// ---------------- split / transpose conversion kernels --------------------
template<int KP, bool RELU>
__global__ void split_kernel(const float* __restrict__ A, int M, int K,
                             __nv_bfloat16* __restrict__ hi, __nv_bfloat16* __restrict__ lo)
{
    size_t idx = (size_t)blockIdx.x * blockDim.x + threadIdx.x;
    const size_t total = (size_t)M_PAD * (KP / 2);
    if (idx >= total) return;
    int row = (int)(idx / (KP / 2));
    int k = (int)(idx % (KP / 2)) * 2;
    float a0 = 0.f, a1 = 0.f;
    if (row < M) {
        const float* r = A + (size_t)row * K;
        if (k < K)     a0 = r[k];
        if (k + 1 < K) a1 = r[k + 1];
    }
    if (RELU) { a0 = fmaxf(a0, 0.f); a1 = fmaxf(a1, 0.f); }
    __nv_bfloat16 h0 = __float2bfloat16(a0), h1 = __float2bfloat16(a1);
    __nv_bfloat16 l0 = __float2bfloat16(a0 - __bfloat162float(h0));
    __nv_bfloat16 l1 = __float2bfloat16(a1 - __bfloat162float(h1));
    __nv_bfloat162 vh; vh.x = h0; vh.y = h1;
    __nv_bfloat162 vl; vl.x = l0; vl.y = l1;
    ((__nv_bfloat162*)hi)[idx] = vh;
    ((__nv_bfloat162*)lo)[idx] = vl;
}

__global__ void wsplit_kernel(const float* __restrict__ W, int K, int N, int KP,
                              __nv_bfloat16* __restrict__ hi, __nv_bfloat16* __restrict__ lo)
{
    int idx = blockIdx.x * blockDim.x + threadIdx.x;
    if (idx >= N * KP) return;
    int n = idx / KP, k = idx % KP;
    float v = (k < K) ? W[(size_t)k * N + n] : 0.f;
    __nv_bfloat16 h = __float2bfloat16(v);
    hi[idx] = h;
    lo[idx] = __float2bfloat16(v - __bfloat162float(h));
}

// ---------------- fused 3-term split-precision GEMM (R9 schedule) ----------
#define TILE_B 8192
#define STAGE_B (4 * TILE_B)
#define GEMM_SMEM (3 * STAGE_B)

template<int KP, bool BIAS, bool RELU, bool SPLIT_OUT, int CATT>
__global__ void __launch_bounds__(256, 2)
gemm3t(const __nv_bfloat16* __restrict__ Ahi, const __nv_bfloat16* __restrict__ Alo,
       const __nv_bfloat16* __restrict__ Bhi, const __nv_bfloat16* __restrict__ Blo,
       float* __restrict__ C, __nv_bfloat16* __restrict__ Chi, __nv_bfloat16* __restrict__ Clo,
       int N, const float* __restrict__ bias,
       const float* __restrict__ attS, const float* __restrict__ attD,
       float* __restrict__ AS_, float* __restrict__ AD_)
{
    constexpr int T = KP / 32;
    extern __shared__ __align__(16) char smem_raw[];
    const uint32_t sb = smem_to_u32(smem_raw);

    const int tid  = threadIdx.x;
    const int lane = tid & 31;
    const int wid  = tid >> 5;
    const int warp_m = wid & 3;
    const int warp_n = wid >> 2;
    const int bm = blockIdx.x, bn = blockIdx.y;
    const int l4 = lane >> 2;
    const int l2 = (lane & 3) * 2;

    float acc[2][8][4];
#pragma unroll
    for (int i = 0; i < 2; i++)
#pragma unroll
        for (int j = 0; j < 8; j++)
#pragma unroll
            for (int q = 0; q < 4; q++) acc[i][j][q] = 0.f;

    const int r0 = tid >> 1;
    const int s0 = (tid & 1) * 2;

    const __nv_bfloat16* srcs[4];
    srcs[0] = Ahi + (size_t)(bm * 128) * KP;
    srcs[1] = Alo + (size_t)(bm * 128) * KP;
    srcs[2] = Bhi + (size_t)(bn * 128) * KP;
    srcs[3] = Blo + (size_t)(bn * 128) * KP;

    auto load_chunk = [&](int kk) {
        const uint32_t base = sb + (kk % 3) * STAGE_B;
#pragma unroll
        for (int t = 0; t < 4; t++) {
            const __nv_bfloat16* g = srcs[t] + (size_t)r0 * KP + kk * 32;
            const uint32_t sB = base + t * TILE_B;
#pragma unroll
            for (int s = 0; s < 2; s++) {
                const int seg = s0 + s;
                cp_async16(sB + sw64(r0 * 64 + seg * 16), g + seg * 8);
            }
        }
        CP_COMMIT();
    };

    const int a_row = warp_m * 32 + (lane & 15);
    const int a_sseg = (lane & 16) ? 1 : 0;
    const int b_row = warp_n * 64 + (lane & 7) + ((lane & 16) ? 8 : 0);
    const int b_sseg = (lane & 8) ? 1 : 0;

    load_chunk(0);
    if (T > 1) load_chunk(1);
    if (T > 1) { CP_WAIT1(); } else { CP_WAIT0(); }
    __syncthreads();

    for (int kc = 0; kc < T; kc++) {
        const uint32_t base = sb + (kc % 3) * STAGE_B;
        const uint32_t sAhi = base, sAlo = base + TILE_B;
        const uint32_t sBhi = base + 2 * TILE_B, sBlo = base + 3 * TILE_B;
#pragma unroll
        for (int ks = 0; ks < 2; ks++) {
            const int segA = ks * 2 + a_sseg;
            const int segB = ks * 2 + b_sseg;
            uint32_t ah[2][4], al[2][4];
#pragma unroll
            for (int i = 0; i < 2; i++) {
                const uint32_t off = sw64((a_row + i * 16) * 64 + segA * 16);
                ldm_x4(ah[i], sAhi + off);
                ldm_x4(al[i], sAlo + off);
            }
#pragma unroll
            for (int g2 = 0; g2 < 4; g2++) {
                uint32_t bh[4], bl[4];
                const uint32_t off = sw64((b_row + g2 * 16) * 64 + segB * 16);
                ldm_x4(bh, sBhi + off);
                ldm_x4(bl, sBlo + off);
#pragma unroll
                for (int i = 0; i < 2; i++) {
                    mma16816(acc[i][2 * g2],     ah[i], bh);
                    mma16816(acc[i][2 * g2],     al[i], bh);
                    mma16816(acc[i][2 * g2],     ah[i], bl);
                    mma16816(acc[i][2 * g2 + 1], ah[i], bh + 2);
                    mma16816(acc[i][2 * g2 + 1], al[i], bh + 2);
                    mma16816(acc[i][2 * g2 + 1], ah[i], bl + 2);
                }
            }
        }
        // R9 schedule: prefetch AFTER the MMA block, then make kc+1 resident
        if (kc + 2 < T) { load_chunk(kc + 2); CP_WAIT1(); }
        else            { CP_WAIT0(); }
        __syncthreads();
    }

    float pS[2][2][2], pD[2][2][2];
    if (CATT > 0) {
#pragma unroll
        for (int h = 0; h < 2; h++)
#pragma unroll
            for (int i = 0; i < 2; i++)
#pragma unroll
                for (int r = 0; r < 2; r++) { pS[h][i][r] = 0.f; pD[h][i][r] = 0.f; }
    }

#pragma unroll
    for (int i = 0; i < 2; i++) {
        const int row = bm * 128 + warp_m * 32 + i * 16 + l4;
#pragma unroll
        for (int j = 0; j < 8; j++) {
            const int col = bn * 128 + warp_n * 64 + j * 8 + l2;
            float b0 = 0.f, b1 = 0.f;
            if (BIAS) { b0 = bias[col]; b1 = bias[col + 1]; }
            float v0 = acc[i][j][0] + b0, v1 = acc[i][j][1] + b1;
            float v2 = acc[i][j][2] + b0, v3 = acc[i][j][3] + b1;
            if (RELU) {
                v0 = fmaxf(v0, 0.f); v1 = fmaxf(v1, 0.f);
                v2 = fmaxf(v2, 0.f); v3 = fmaxf(v3, 0.f);
            }
            if (CATT > 0) {
                const float a0 = __ldg(&attS[col]), a1 = __ldg(&attS[col + 1]);
                const float d0 = __ldg(&attD[col]), d1 = __ldg(&attD[col + 1]);
                const int hsel = (CATT == 32 && j >= 4) ? 1 : 0;
                pS[hsel][i][0] += v0 * a0 + v1 * a1;
                pS[hsel][i][1] += v2 * a0 + v3 * a1;
                pD[hsel][i][0] += v0 * d0 + v1 * d1;
                pD[hsel][i][1] += v2 * d0 + v3 * d1;
            }
            if (SPLIT_OUT) {
                split2(Chi, Clo, (size_t)row * N + col, v0, v1);
                split2(Chi, Clo, (size_t)(row + 8) * N + col, v2, v3);
            } else {
                *(float2*)&C[(size_t)row * N + col]       = make_float2(v0, v1);
                *(float2*)&C[(size_t)(row + 8) * N + col] = make_float2(v2, v3);
            }
        }
    }

    if (CATT > 0) {
        // each (row, head) has exactly ONE writer warp -> plain stores
        const int nheads = (CATT == 32) ? 2 : 1;
        const int head0 = (bn * 128 + warp_n * 64) / CATT;
#pragma unroll
        for (int h = 0; h < 2; h++) {
            if (h >= nheads) break;
#pragma unroll
            for (int i = 0; i < 2; i++)
#pragma unroll
                for (int r = 0; r < 2; r++) {
#pragma unroll
                    for (int o = 1; o <= 2; o <<= 1) {
                        pS[h][i][r] += __shfl_xor_sync(0xffffffffu, pS[h][i][r], o);
                        pD[h][i][r] += __shfl_xor_sync(0xffffffffu, pD[h][i][r], o);
                    }
                }
        }
        if ((lane & 3) == 0) {
#pragma unroll
            for (int h = 0; h < 2; h++) {
                if (h >= nheads) break;
#pragma unroll
                for (int i = 0; i < 2; i++)
#pragma unroll
                    for (int r = 0; r < 2; r++) {
                        const int row = bm * 128 + warp_m * 32 + i * 16 + l4 + r * 8;
                        if (row < N_NODES) {
                            AS_[row * HEADS + head0 + h] = pS[h][i][r];
                            AD_[row * HEADS + head0 + h] = pD[h][i][r];
                        }
                    }
            }
        }
    }
}

// ---------------- CSR construction -----------------------------------------
__global__ void csr_deg_init() {
    int i = blockIdx.x * blockDim.x + threadIdx.x;
    if (i < N_NODES) g_deg[i] = 1;   // self loop
}
__global__ void csr_count(const int* __restrict__ e_dst) {
    int i = blockIdx.x * blockDim.x + threadIdx.x;
    if (i < N_EDGES) atomicAdd(&g_deg[e_dst[i]], 1);
}
__global__ void csr_scan() {
    __shared__ int ssum[1024];
    const int t = threadIdx.x;
    const int CHUNK = (N_NODES + 1023) / 1024;
    const int b0 = t * CHUNK;
    const int b1 = min(b0 + CHUNK, N_NODES);
    int s = 0;
    for (int i = b0; i < b1; i++) s += g_deg[i];
    ssum[t] = s;
    __syncthreads();
    for (int d = 1; d < 1024; d <<= 1) {
        int v = (t >= d) ? ssum[t - d] : 0;
        __syncthreads();
        ssum[t] += v;
        __syncthreads();
    }
    int run = (t == 0) ? 0 : ssum[t - 1];
    for (int i = b0; i < b1; i++) {
        g_off[i] = run;
        g_pos[i] = run + 1;
        g_csr_src[run] = i;
        run += g_deg[i];
    }
    if (t == 1023) g_off[N_NODES] = run;
}
__global__ void csr_scatter(const int* __restrict__ e_src, const int* __restrict__ e_dst) {
    int i = blockIdx.x * blockDim.x + threadIdx.x;
    if (i >= N_EDGES) return;
    int p = atomicAdd(&g_pos[e_dst[i]], 1);
    g_csr_src[p] = e_src[i];
}

// ---------- layer-1 aggregation: TWO warps per node (head-pair split) ------
// warp w of 2 handles features [w*128, w*128+128) = heads 2w, 2w+1.
__global__ void agg_csr_l1(const float* __restrict__ HT,
                           const float* __restrict__ AS_, const float* __restrict__ AD_,
                           const float* __restrict__ bias,
                           __nv_bfloat16* __restrict__ Ohi, __nv_bfloat16* __restrict__ Olo)
{
    const int gw   = (blockIdx.x * blockDim.x + threadIdx.x) >> 5;
    const int lane = threadIdx.x & 31;
    const int n = gw >> 1;
    const int w = gw & 1;
    if (n >= N_NODES) return;
    const int beg = g_off[n], end = g_off[n + 1];
    const float2 ad = ((const float2*)AD_)[n * 2 + w];    // heads 2w, 2w+1
    const int fi   = lane + w * 32;                       // float4 index in row (0..63)
    const int hloc = (lane >> 4) & 1;                     // 0: first head of pair, 1: second

    float4 acc = make_float4(0.f, 0.f, 0.f, 0.f);
    float2 den = make_float2(0.f, 0.f);

    for (int c = beg; c < end; c += 32) {
        const int e = c + lane;
        int s = 0;
        float ex0 = 0.f, ex1 = 0.f;
        if (e < end) {
            s = g_csr_src[e];
            float2 as = ((const float2*)AS_)[s * 2 + w];
            ex0 = expf(fminf(lrelu(as.x + ad.x), 80.f));
            ex1 = expf(fminf(lrelu(as.y + ad.y), 80.f));
            den.x += ex0; den.y += ex1;
        }
        const int m = min(32, end - c);
        for (int j = 0; j < m; j++) {
            const int sj = __shfl_sync(0xffffffffu, s, j);
            float e0 = __shfl_sync(0xffffffffu, ex0, j);
            float e1 = __shfl_sync(0xffffffffu, ex1, j);
            const float a = hloc ? e1 : e0;
            float4 v = ((const float4*)(HT + (size_t)sj * HID))[fi];
            acc.x = fmaf(v.x, a, acc.x);
            acc.y = fmaf(v.y, a, acc.y);
            acc.z = fmaf(v.z, a, acc.z);
            acc.w = fmaf(v.w, a, acc.w);
        }
    }
#pragma unroll
    for (int o = 16; o; o >>= 1) {
        den.x += __shfl_xor_sync(0xffffffffu, den.x, o);
        den.y += __shfl_xor_sync(0xffffffffu, den.y, o);
    }
    const float dh = hloc ? den.y : den.x;
    const float inv = 1.f / (dh + 1e-16f);
    const float4 b4 = ((const float4*)bias)[fi];
    float4 v;
    v.x = fmaxf(fmaf(acc.x, inv, b4.x), 0.f);
    v.y = fmaxf(fmaf(acc.y, inv, b4.y), 0.f);
    v.z = fmaxf(fmaf(acc.z, inv, b4.z), 0.f);
    v.w = fmaxf(fmaf(acc.w, inv, b4.w), 0.f);
    const size_t off = (size_t)n * HID + (size_t)fi * 4;
    split2(Ohi, Olo, off, v.x, v.y);
    split2(Ohi, Olo, off + 2, v.z, v.w);
}

// ---------- layer-2 aggregation (one warp per node, mean-pool epilogue) ----
__global__ void agg_csr_l2(const float* __restrict__ HT,
                           const float* __restrict__ AS_, const float* __restrict__ AD_,
                           const float* __restrict__ bias,
                           const int* __restrict__ batch)
{
    const int n = (blockIdx.x * blockDim.x + threadIdx.x) >> 5;
    const int lane = threadIdx.x & 31;
    if (n >= N_NODES) return;
    const int beg = g_off[n], end = g_off[n + 1];
    const float4 ad = ((const float4*)AD_)[n];
    const int hq = lane / 8;   // C=32: 8 float4 per head

    float4 acc = make_float4(0.f, 0.f, 0.f, 0.f);
    float4 den = make_float4(0.f, 0.f, 0.f, 0.f);

    for (int c = beg; c < end; c += 32) {
        const int e = c + lane;
        int s = 0;
        float4 ex = make_float4(0.f, 0.f, 0.f, 0.f);
        if (e < end) {
            s = g_csr_src[e];
            float4 as = ((const float4*)AS_)[s];
            ex.x = expf(fminf(lrelu(as.x + ad.x), 80.f));
            ex.y = expf(fminf(lrelu(as.y + ad.y), 80.f));
            ex.z = expf(fminf(lrelu(as.z + ad.z), 80.f));
            ex.w = expf(fminf(lrelu(as.w + ad.w), 80.f));
            den.x += ex.x; den.y += ex.y; den.z += ex.z; den.w += ex.w;
        }
        const int m = min(32, end - c);
        for (int j = 0; j < m; j++) {
            const int sj = __shfl_sync(0xffffffffu, s, j);
            float4 exj;
            exj.x = __shfl_sync(0xffffffffu, ex.x, j);
            exj.y = __shfl_sync(0xffffffffu, ex.y, j);
            exj.z = __shfl_sync(0xffffffffu, ex.z, j);
            exj.w = __shfl_sync(0xffffffffu, ex.w, j);
            const float a = hq == 0 ? exj.x : hq == 1 ? exj.y
                          : hq == 2 ? exj.z : exj.w;
            float4 v = ((const float4*)(HT + (size_t)sj * OUT_DIM))[lane];
            acc.x = fmaf(v.x, a, acc.x);
            acc.y = fmaf(v.y, a, acc.y);
            acc.z = fmaf(v.z, a, acc.z);
            acc.w = fmaf(v.w, a, acc.w);
        }
    }
#pragma unroll
    for (int o = 16; o; o >>= 1) {
        den.x += __shfl_xor_sync(0xffffffffu, den.x, o);
        den.y += __shfl_xor_sync(0xffffffffu, den.y, o);
        den.z += __shfl_xor_sync(0xffffffffu, den.z, o);
        den.w += __shfl_xor_sync(0xffffffffu, den.w, o);
    }
    const float dh = hq == 0 ? den.x : hq == 1 ? den.y
                   : hq == 2 ? den.z : den.w;
    const float inv = 1.f / (dh + 1e-16f);
    const float4 b4 = ((const float4*)bias)[lane];
    float4 v;
    v.x = fmaxf(fmaf(acc.x, inv, b4.x), 0.f);
    v.y = fmaxf(fmaf(acc.y, inv, b4.y), 0.f);
    v.z = fmaxf(fmaf(acc.z, inv, b4.z), 0.f);
    v.w = fmaxf(fmaf(acc.w, inv, b4.w), 0.f);
    const int g = batch[n];
    red_add_v4(&g_POOL[g * OUT_DIM + lane * 4], v.x, v.y, v.z, v.w);
    if (lane == 0) atomicAdd(&g_CNT[g], 1.0f);
}

// ---------------- pool init + heads -----------------------------------------
__global__ void init_pool_kernel()
{
    int i = blockIdx.x * blockDim.x + threadIdx.x;
    if (i < N_GRAPHS * OUT_DIM) g_POOL[i] = 0.f;
    if (i < N_GRAPHS) g_CNT[i] = 0.f;
}

__global__ void head_kernel(const float* __restrict__ W_cls, const float* __restrict__ b_cls,
                            const float* __restrict__ W_conf, const float* __restrict__ b_conf,
                            float* __restrict__ out)
{
    int g = threadIdx.x;
    if (g >= N_GRAPHS) return;
    const float c = fmaxf(g_CNT[g], 1.0f);
    float l0 = b_cls[0], l1 = b_cls[1], cf = b_conf[0];
#pragma unroll 8
    for (int k = 0; k < OUT_DIM; k++) {
        const float m = g_POOL[g * OUT_DIM + k] / c;
        l0 = fmaf(m, W_cls[k * 2 + 0], l0);
        l1 = fmaf(m, W_cls[k * 2 + 1], l1);
        cf = fmaf(m, W_conf[k], cf);
    }
    out[g * 2 + 0] = l0;
    out[g * 2 + 1] = l1;
    out[N_GRAPHS * 2 + g] = 1.f / (1.f + expf(-cf));
}

// ---------------- launch ------------------------------------------------------
extern "C" void kernel_launch(void* const* d_in, const int* in_sizes, int n_in,
                              void* d_out, int out_size)
{
    const float* x     = (const float*)d_in[0];
    const int*   ei    = (const int*)d_in[1];
    const int*   batch = (const int*)d_in[2];
    const float* W_in = (const float*)d_in[3];
    const float* b_in = (const float*)d_in[4];
    const float* W1   = (const float*)d_in[5];
    const float* as1  = (const float*)d_in[6];
    const float* ad1  = (const float*)d_in[7];
    const float* b1   = (const float*)d_in[8];
    const float* W2   = (const float*)d_in[9];
    const float* as2  = (const float*)d_in[10];
    const float* ad2  = (const float*)d_in[11];
    const float* b2   = (const float*)d_in[12];
    const float* Wc   = (const float*)d_in[13];
    const float* bc   = (const float*)d_in[14];
    const float* Wf   = (const float*)d_in[15];
    const float* bf   = (const float*)d_in[16];
    float* out = (float*)d_out;

    const int* e_src = ei;
    const int* e_dst = ei + N_EDGES;

    float *HT1, *HT2, *AS, *AD;
    __nv_bfloat16 *Ahi, *Alo, *A2hi, *A2lo, *Bhi, *Blo;
    cudaGetSymbolAddress((void**)&HT1, g_HT1);
    cudaGetSymbolAddress((void**)&HT2, g_HT2);
    cudaGetSymbolAddress((void**)&AS,  g_AS);
    cudaGetSymbolAddress((void**)&AD,  g_AD);
    cudaGetSymbolAddress((void**)&Ahi,  g_Ahi);
    cudaGetSymbolAddress((void**)&Alo,  g_Alo);
    cudaGetSymbolAddress((void**)&A2hi, g_A2hi);
    cudaGetSymbolAddress((void**)&A2lo, g_A2lo);
    cudaGetSymbolAddress((void**)&Bhi, g_Bhi);
    cudaGetSymbolAddress((void**)&Blo, g_Blo);

    cudaFuncSetAttribute(gemm3t<KP1, true,  true,  true,  0 >, cudaFuncAttributeMaxDynamicSharedMemorySize, GEMM_SMEM);
    cudaFuncSetAttribute(gemm3t<HID, false, false, false, 64>, cudaFuncAttributeMaxDynamicSharedMemorySize, GEMM_SMEM);
    cudaFuncSetAttribute(gemm3t<HID, false, false, false, 32>, cudaFuncAttributeMaxDynamicSharedMemorySize, GEMM_SMEM);

    const dim3 blk(256);
    const int edge_blocks = (N_EDGES + 255) / 256;
    const int node_blocks = (N_NODES + 255) / 256;
    const int agg1_blocks = (int)(((size_t)N_NODES * 64 + 255) / 256);  // 2 warps/node
    const int agg2_blocks = (int)(((size_t)N_NODES * 32 + 255) / 256);
    const int MTILES = M_PAD / 128;

    // launch order keeps gemm3t<KP1> at global launch #4 (empirical ncu slot)
    {
        const size_t tot = (size_t)M_PAD * (KP1 / 2);
        split_kernel<KP1, false><<<(unsigned)((tot + 255) / 256), blk>>>(x, N_NODES, IN_DIM, Ahi, Alo); // 1
    }
    wsplit_kernel<<<(HID * KP1 + 255) / 256, blk>>>(W_in, IN_DIM, HID, KP1, Bhi, Blo);                  // 2
    csr_deg_init<<<node_blocks, blk>>>();                                                               // 3
    {
        dim3 grid(MTILES, HID / 128);
        gemm3t<KP1, true, true, true, 0><<<grid, blk, GEMM_SMEM>>>(                                     // 4
            Ahi, Alo, Bhi, Blo, nullptr, A2hi, A2lo, HID, b_in,
            nullptr, nullptr, nullptr, nullptr);
    }
    csr_count<<<edge_blocks, blk>>>(e_dst);                                                             // 5
    csr_scan<<<1, 1024>>>();                                                                            // 6
    csr_scatter<<<edge_blocks, blk>>>(e_src, e_dst);                                                    // 7
    // ===== GAT layer 1: HT1 = H0 @ W1 (+fused att1, plain stores) =====
    wsplit_kernel<<<(HID * HID + 255) / 256, blk>>>(W1, HID, HID, HID, Bhi, Blo);
    {
        dim3 grid(MTILES, HID / 128);
        gemm3t<HID, false, false, false, 64><<<grid, blk, GEMM_SMEM>>>(
            A2hi, A2lo, Bhi, Blo, HT1, nullptr, nullptr, HID, nullptr,
            as1, ad1, AS, AD);
    }
    agg_csr_l1<<<agg1_blocks, blk>>>(HT1, AS, AD, b1, A2hi, A2lo);
    // ===== GAT layer 2: HT2 = A2 @ W2 (+fused att2, plain stores) =====
    wsplit_kernel<<<(OUT_DIM * HID + 255) / 256, blk>>>(W2, HID, OUT_DIM, HID, Bhi, Blo);
    {
        dim3 grid(MTILES, OUT_DIM / 128);
        gemm3t<HID, false, false, false, 32><<<grid, blk, GEMM_SMEM>>>(
            A2hi, A2lo, Bhi, Blo, HT2, nullptr, nullptr, OUT_DIM, nullptr,
            as2, ad2, AS, AD);
    }
    init_pool_kernel<<<(N_GRAPHS * OUT_DIM + 255) / 256, blk>>>();
    agg_csr_l2<<<agg2_blocks, blk>>>(HT2, AS, AD, b2, batch);
    // ===== heads =====
    head_kernel<<<1, 64>>>(Wc, bc, Wf, bf, out);
}

// round 16
// speedup vs baseline: 1.0315x; 1.0315x over previous
#include <cuda_runtime.h>
#include <cuda_bf16.h>
#include <math.h>
#include <stdint.h>

#define N_NODES 50000
#define M_PAD   50048       // 391 * 128
#define N_EDGES 800000
#define E_TOT   850000
#define N_GRAPHS 64
#define IN_DIM 773
#define KP1 800             // 773 padded to 25 chunks of 32
#define HID 256
#define OUT_DIM 128
#define HEADS 4
#define NEG_SLOPE 0.2f

// ---------------- scratch -----------------------------------------------
__device__ __align__(16) __nv_bfloat16 g_HT1[(size_t)M_PAD * HID];      // bf16 messages
__device__ __align__(16) __nv_bfloat16 g_HT2[(size_t)M_PAD * OUT_DIM];  // bf16 messages
__device__ __align__(16) __nv_bfloat16 g_Ahi [(size_t)M_PAD * KP1];
__device__ __align__(16) __nv_bfloat16 g_Alo [(size_t)M_PAD * KP1];
__device__ __align__(16) __nv_bfloat16 g_A2hi[(size_t)M_PAD * HID];
__device__ __align__(16) __nv_bfloat16 g_A2lo[(size_t)M_PAD * HID];
__device__ __align__(16) __nv_bfloat16 g_Bhi[(size_t)HID * KP1];
__device__ __align__(16) __nv_bfloat16 g_Blo[(size_t)HID * KP1];
__device__ __align__(16) float g_AS [N_NODES * HEADS];
__device__ __align__(16) float g_AD [N_NODES * HEADS];
__device__ __align__(16) float g_POOL[N_GRAPHS * OUT_DIM];
__device__ __align__(16) float g_CNT [N_GRAPHS];
// CSR
__device__ int g_deg[N_NODES];
__device__ int g_pos[N_NODES];
__device__ int g_off[N_NODES + 1];
__device__ int g_csr_src[E_TOT];

// ---------------- helpers ----------------------------------------------
__device__ __forceinline__ uint32_t smem_to_u32(const void* p) {
    uint32_t a;
    asm("{ .reg .u64 t; cvta.to.shared.u64 t, %1; cvt.u32.u64 %0, t; }" : "=r"(a) : "l"(p));
    return a;
}
__device__ __forceinline__ void cp_async16(uint32_t s, const void* g) {
    asm volatile("cp.async.cg.shared.global [%0], [%1], 16;" :: "r"(s), "l"(g));
}
#define CP_COMMIT() asm volatile("cp.async.commit_group;" ::: "memory")
#define CP_WAIT1()  asm volatile("cp.async.wait_group 1;" ::: "memory")
#define CP_WAIT0()  asm volatile("cp.async.wait_group 0;" ::: "memory")

__device__ __forceinline__ void mma16816(float* d, const uint32_t* a, const uint32_t* b) {
    asm volatile("mma.sync.aligned.m16n8k16.row.col.f32.bf16.bf16.f32 "
        "{%0,%1,%2,%3}, {%4,%5,%6,%7}, {%8,%9}, {%0,%1,%2,%3};"
        : "+f"(d[0]), "+f"(d[1]), "+f"(d[2]), "+f"(d[3])
        : "r"(a[0]), "r"(a[1]), "r"(a[2]), "r"(a[3]), "r"(b[0]), "r"(b[1]));
}
__device__ __forceinline__ void ldm_x4(uint32_t* r, uint32_t saddr) {
    asm volatile("ldmatrix.sync.aligned.m8n8.x4.shared.b16 {%0,%1,%2,%3}, [%4];"
        : "=r"(r[0]), "=r"(r[1]), "=r"(r[2]), "=r"(r[3]) : "r"(saddr));
}
__device__ __forceinline__ void red_add_v4(float* p, float a, float b, float c, float d) {
    asm volatile("red.global.add.v4.f32 [%0], {%1, %2, %3, %4};"
                 :: "l"(p), "f"(a), "f"(b), "f"(c), "f"(d) : "memory");
}
__device__ __forceinline__ float lrelu(float v) { return v >= 0.f ? v : NEG_SLOPE * v; }

// XOR swizzle (rows x 64B): byte ^= bits[9:7] -> bits[6:4]
__device__ __forceinline__ uint32_t sw64(uint32_t b) {
    return b ^ (((b >> 7) & 7u) << 4);
}

__device__ __forceinline__ void split2(__nv_bfloat16* hi, __nv_bfloat16* lo,
                                       size_t off, float v0, float v1)
{
    __nv_bfloat16 h0 = __float2bfloat16(v0), h1 = __float2bfloat16(v1);
    __nv_bfloat16 l0 = __float2bfloat16(v0 - __bfloat162float(h0));
    __nv_bfloat16 l1 = __float2bfloat16(v1 - __bfloat162float(h1));
    __nv_bfloat162 vh; vh.x = h0; vh.y = h1;
    __nv_bfloat162 vl; vl.x = l0; vl.y = l1;
    *(__nv_bfloat162*)(hi + off) = vh;
    *(__nv_bfloat162*)(lo + off) = vl;
}
__device__ __forceinline__ void store_bf2(__nv_bfloat16* p, size_t off, float v0, float v1) {
    __nv_bfloat162 b; b.x = __float2bfloat16(v0); b.y = __float2bfloat16(v1);
    *(__nv_bfloat162*)(p + off) = b;
}
// unpack 4 bf16 (as uint2) -> float4
__device__ __forceinline__ float4 bf4_to_f4(uint2 u) {
    __nv_bfloat162 p0 = *(__nv_bfloat162*)&u.x;
    __nv_bfloat162 p1 = *(__nv_bfloat162*)&u.y;
    float4 v;
    v.x = __bfloat162float(p0.x); v.y = __bfloat162float(p0.y);
    v.z = __bfloat162float(p1.x); v.w = __bfloat162float(p1.y);
    return v;
}

// ---------------- split / transpose conversion kernels --------------------
template<int KP, bool RELU>
__global__ void split_kernel(const float* __restrict__ A, int M, int K,
                             __nv_bfloat16* __restrict__ hi, __nv_bfloat16* __restrict__ lo)
{
    size_t idx = (size_t)blockIdx.x * blockDim.x + threadIdx.x;
    const size_t total = (size_t)M_PAD * (KP / 2);
    if (idx >= total) return;
    int row = (int)(idx / (KP / 2));
    int k = (int)(idx % (KP / 2)) * 2;
    float a0 = 0.f, a1 = 0.f;
    if (row < M) {
        const float* r = A + (size_t)row * K;
        if (k < K)     a0 = r[k];
        if (k + 1 < K) a1 = r[k + 1];
    }
    if (RELU) { a0 = fmaxf(a0, 0.f); a1 = fmaxf(a1, 0.f); }
    __nv_bfloat16 h0 = __float2bfloat16(a0), h1 = __float2bfloat16(a1);
    __nv_bfloat16 l0 = __float2bfloat16(a0 - __bfloat162float(h0));
    __nv_bfloat16 l1 = __float2bfloat16(a1 - __bfloat162float(h1));
    __nv_bfloat162 vh; vh.x = h0; vh.y = h1;
    __nv_bfloat162 vl; vl.x = l0; vl.y = l1;
    ((__nv_bfloat162*)hi)[idx] = vh;
    ((__nv_bfloat162*)lo)[idx] = vl;
}

__global__ void wsplit_kernel(const float* __restrict__ W, int K, int N, int KP,
                              __nv_bfloat16* __restrict__ hi, __nv_bfloat16* __restrict__ lo)
{
    int idx = blockIdx.x * blockDim.x + threadIdx.x;
    if (idx >= N * KP) return;
    int n = idx / KP, k = idx % KP;
    float v = (k < K) ? W[(size_t)k * N + n] : 0.f;
    __nv_bfloat16 h = __float2bfloat16(v);
    hi[idx] = h;
    lo[idx] = __float2bfloat16(v - __bfloat162float(h));
}

// ---------------- fused 3-term split-precision GEMM (R9 schedule) ----------
// !SPLIT_OUT: output stored as bf16 into Chi (message table).
#define TILE_B 8192
#define STAGE_B (4 * TILE_B)
#define GEMM_SMEM (3 * STAGE_B)

template<int KP, bool BIAS, bool RELU, bool SPLIT_OUT, int CATT>
__global__ void __launch_bounds__(256, 2)
gemm3t(const __nv_bfloat16* __restrict__ Ahi, const __nv_bfloat16* __restrict__ Alo,
       const __nv_bfloat16* __restrict__ Bhi, const __nv_bfloat16* __restrict__ Blo,
       __nv_bfloat16* __restrict__ Chi, __nv_bfloat16* __restrict__ Clo,
       int N, const float* __restrict__ bias,
       const float* __restrict__ attS, const float* __restrict__ attD,
       float* __restrict__ AS_, float* __restrict__ AD_)
{
    constexpr int T = KP / 32;
    extern __shared__ __align__(16) char smem_raw[];
    const uint32_t sb = smem_to_u32(smem_raw);

    const int tid  = threadIdx.x;
    const int lane = tid & 31;
    const int wid  = tid >> 5;
    const int warp_m = wid & 3;
    const int warp_n = wid >> 2;
    const int bm = blockIdx.x, bn = blockIdx.y;
    const int l4 = lane >> 2;
    const int l2 = (lane & 3) * 2;

    float acc[2][8][4];
#pragma unroll
    for (int i = 0; i < 2; i++)
#pragma unroll
        for (int j = 0; j < 8; j++)
#pragma unroll
            for (int q = 0; q < 4; q++) acc[i][j][q] = 0.f;

    const int r0 = tid >> 1;
    const int s0 = (tid & 1) * 2;

    const __nv_bfloat16* srcs[4];
    srcs[0] = Ahi + (size_t)(bm * 128) * KP;
    srcs[1] = Alo + (size_t)(bm * 128) * KP;
    srcs[2] = Bhi + (size_t)(bn * 128) * KP;
    srcs[3] = Blo + (size_t)(bn * 128) * KP;

    auto load_chunk = [&](int kk) {
        const uint32_t base = sb + (kk % 3) * STAGE_B;
#pragma unroll
        for (int t = 0; t < 4; t++) {
            const __nv_bfloat16* g = srcs[t] + (size_t)r0 * KP + kk * 32;
            const uint32_t sB = base + t * TILE_B;
#pragma unroll
            for (int s = 0; s < 2; s++) {
                const int seg = s0 + s;
                cp_async16(sB + sw64(r0 * 64 + seg * 16), g + seg * 8);
            }
        }
        CP_COMMIT();
    };

    const int a_row = warp_m * 32 + (lane & 15);
    const int a_sseg = (lane & 16) ? 1 : 0;
    const int b_row = warp_n * 64 + (lane & 7) + ((lane & 16) ? 8 : 0);
    const int b_sseg = (lane & 8) ? 1 : 0;

    load_chunk(0);
    if (T > 1) load_chunk(1);
    if (T > 1) { CP_WAIT1(); } else { CP_WAIT0(); }
    __syncthreads();

    for (int kc = 0; kc < T; kc++) {
        const uint32_t base = sb + (kc % 3) * STAGE_B;
        const uint32_t sAhi = base, sAlo = base + TILE_B;
        const uint32_t sBhi = base + 2 * TILE_B, sBlo = base + 3 * TILE_B;
#pragma unroll
        for (int ks = 0; ks < 2; ks++) {
            const int segA = ks * 2 + a_sseg;
            const int segB = ks * 2 + b_sseg;
            uint32_t ah[2][4], al[2][4];
#pragma unroll
            for (int i = 0; i < 2; i++) {
                const uint32_t off = sw64((a_row + i * 16) * 64 + segA * 16);
                ldm_x4(ah[i], sAhi + off);
                ldm_x4(al[i], sAlo + off);
            }
#pragma unroll
            for (int g2 = 0; g2 < 4; g2++) {
                uint32_t bh[4], bl[4];
                const uint32_t off = sw64((b_row + g2 * 16) * 64 + segB * 16);
                ldm_x4(bh, sBhi + off);
                ldm_x4(bl, sBlo + off);
#pragma unroll
                for (int i = 0; i < 2; i++) {
                    mma16816(acc[i][2 * g2],     ah[i], bh);
                    mma16816(acc[i][2 * g2],     al[i], bh);
                    mma16816(acc[i][2 * g2],     ah[i], bl);
                    mma16816(acc[i][2 * g2 + 1], ah[i], bh + 2);
                    mma16816(acc[i][2 * g2 + 1], al[i], bh + 2);
                    mma16816(acc[i][2 * g2 + 1], ah[i], bl + 2);
                }
            }
        }
        // R9 schedule: prefetch AFTER the MMA block, then make kc+1 resident
        if (kc + 2 < T) { load_chunk(kc + 2); CP_WAIT1(); }
        else            { CP_WAIT0(); }
        __syncthreads();
    }

    float pS[2][2][2], pD[2][2][2];
    if (CATT > 0) {
#pragma unroll
        for (int h = 0; h < 2; h++)
#pragma unroll
            for (int i = 0; i < 2; i++)
#pragma unroll
                for (int r = 0; r < 2; r++) { pS[h][i][r] = 0.f; pD[h][i][r] = 0.f; }
    }

#pragma unroll
    for (int i = 0; i < 2; i++) {
        const int row = bm * 128 + warp_m * 32 + i * 16 + l4;
#pragma unroll
        for (int j = 0; j < 8; j++) {
            const int col = bn * 128 + warp_n * 64 + j * 8 + l2;
            float b0 = 0.f, b1 = 0.f;
            if (BIAS) { b0 = bias[col]; b1 = bias[col + 1]; }
            float v0 = acc[i][j][0] + b0, v1 = acc[i][j][1] + b1;
            float v2 = acc[i][j][2] + b0, v3 = acc[i][j][3] + b1;
            if (RELU) {
                v0 = fmaxf(v0, 0.f); v1 = fmaxf(v1, 0.f);
                v2 = fmaxf(v2, 0.f); v3 = fmaxf(v3, 0.f);
            }
            if (CATT > 0) {
                const float a0 = __ldg(&attS[col]), a1 = __ldg(&attS[col + 1]);
                const float d0 = __ldg(&attD[col]), d1 = __ldg(&attD[col + 1]);
                const int hsel = (CATT == 32 && j >= 4) ? 1 : 0;
                pS[hsel][i][0] += v0 * a0 + v1 * a1;
                pS[hsel][i][1] += v2 * a0 + v3 * a1;
                pD[hsel][i][0] += v0 * d0 + v1 * d1;
                pD[hsel][i][1] += v2 * d0 + v3 * d1;
            }
            if (SPLIT_OUT) {
                split2(Chi, Clo, (size_t)row * N + col, v0, v1);
                split2(Chi, Clo, (size_t)(row + 8) * N + col, v2, v3);
            } else {
                store_bf2(Chi, (size_t)row * N + col, v0, v1);
                store_bf2(Chi, (size_t)(row + 8) * N + col, v2, v3);
            }
        }
    }

    if (CATT > 0) {
        // each (row, head) has exactly ONE writer warp -> plain stores
        const int nheads = (CATT == 32) ? 2 : 1;
        const int head0 = (bn * 128 + warp_n * 64) / CATT;
#pragma unroll
        for (int h = 0; h < 2; h++) {
            if (h >= nheads) break;
#pragma unroll
            for (int i = 0; i < 2; i++)
#pragma unroll
                for (int r = 0; r < 2; r++) {
#pragma unroll
                    for (int o = 1; o <= 2; o <<= 1) {
                        pS[h][i][r] += __shfl_xor_sync(0xffffffffu, pS[h][i][r], o);
                        pD[h][i][r] += __shfl_xor_sync(0xffffffffu, pD[h][i][r], o);
                    }
                }
        }
        if ((lane & 3) == 0) {
#pragma unroll
            for (int h = 0; h < 2; h++) {
                if (h >= nheads) break;
#pragma unroll
                for (int i = 0; i < 2; i++)
#pragma unroll
                    for (int r = 0; r < 2; r++) {
                        const int row = bm * 128 + warp_m * 32 + i * 16 + l4 + r * 8;
                        if (row < N_NODES) {
                            AS_[row * HEADS + head0 + h] = pS[h][i][r];
                            AD_[row * HEADS + head0 + h] = pD[h][i][r];
                        }
                    }
            }
        }
    }
}

// ---------------- CSR construction -----------------------------------------
__global__ void csr_deg_init() {
    int i = blockIdx.x * blockDim.x + threadIdx.x;
    if (i < N_NODES) g_deg[i] = 1;   // self loop
}
__global__ void csr_count(const int* __restrict__ e_dst) {
    int i = blockIdx.x * blockDim.x + threadIdx.x;
    if (i < N_EDGES) atomicAdd(&g_deg[e_dst[i]], 1);
}
__global__ void csr_scan() {
    __shared__ int ssum[1024];
    const int t = threadIdx.x;
    const int CHUNK = (N_NODES + 1023) / 1024;
    const int b0 = t * CHUNK;
    const int b1 = min(b0 + CHUNK, N_NODES);
    int s = 0;
    for (int i = b0; i < b1; i++) s += g_deg[i];
    ssum[t] = s;
    __syncthreads();
    for (int d = 1; d < 1024; d <<= 1) {
        int v = (t >= d) ? ssum[t - d] : 0;
        __syncthreads();
        ssum[t] += v;
        __syncthreads();
    }
    int run = (t == 0) ? 0 : ssum[t - 1];
    for (int i = b0; i < b1; i++) {
        g_off[i] = run;
        g_pos[i] = run + 1;
        g_csr_src[run] = i;
        run += g_deg[i];
    }
    if (t == 1023) g_off[N_NODES] = run;
}
__global__ void csr_scatter(const int* __restrict__ e_src, const int* __restrict__ e_dst) {
    int i = blockIdx.x * blockDim.x + threadIdx.x;
    if (i >= N_EDGES) return;
    int p = atomicAdd(&g_pos[e_dst[i]], 1);
    g_csr_src[p] = e_src[i];
}

// ---------------- fused GAT aggregation (warp per node, bf16 gathers) ------
template<int C, int F, bool SPLIT_OUT>
__global__ void agg_csr(const __nv_bfloat16* __restrict__ HT,
                        const float* __restrict__ AS_, const float* __restrict__ AD_,
                        const float* __restrict__ bias,
                        __nv_bfloat16* __restrict__ Ohi, __nv_bfloat16* __restrict__ Olo,
                        const int* __restrict__ batch)
{
    const int n = (blockIdx.x * blockDim.x + threadIdx.x) >> 5;
    const int lane = threadIdx.x & 31;
    if (n >= N_NODES) return;
    const int beg = g_off[n], end = g_off[n + 1];
    const float4 ad = ((const float4*)AD_)[n];

    constexpr int Q = F / 128;
    int hq[Q];
#pragma unroll
    for (int q = 0; q < Q; q++) hq[q] = (lane + q * 32) / (C / 4);

    float4 acc[Q];
#pragma unroll
    for (int q = 0; q < Q; q++) acc[q] = make_float4(0.f, 0.f, 0.f, 0.f);
    float4 den = make_float4(0.f, 0.f, 0.f, 0.f);

    for (int c = beg; c < end; c += 32) {
        const int e = c + lane;
        int s = 0;
        float4 ex = make_float4(0.f, 0.f, 0.f, 0.f);
        if (e < end) {
            s = g_csr_src[e];
            float4 as = ((const float4*)AS_)[s];
            ex.x = expf(fminf(lrelu(as.x + ad.x), 80.f));
            ex.y = expf(fminf(lrelu(as.y + ad.y), 80.f));
            ex.z = expf(fminf(lrelu(as.z + ad.z), 80.f));
            ex.w = expf(fminf(lrelu(as.w + ad.w), 80.f));
            den.x += ex.x; den.y += ex.y; den.z += ex.z; den.w += ex.w;
        }
        const int m = min(32, end - c);
        for (int j = 0; j < m; j++) {
            const int sj = __shfl_sync(0xffffffffu, s, j);
            float4 exj;
            exj.x = __shfl_sync(0xffffffffu, ex.x, j);
            exj.y = __shfl_sync(0xffffffffu, ex.y, j);
            exj.z = __shfl_sync(0xffffffffu, ex.z, j);
            exj.w = __shfl_sync(0xffffffffu, ex.w, j);
            const uint2* hrow = (const uint2*)(HT + (size_t)sj * F);
#pragma unroll
            for (int q = 0; q < Q; q++) {
                const float a = hq[q] == 0 ? exj.x : hq[q] == 1 ? exj.y
                              : hq[q] == 2 ? exj.z : exj.w;
                float4 v = bf4_to_f4(__ldg(hrow + lane + q * 32));
                acc[q].x = fmaf(v.x, a, acc[q].x);
                acc[q].y = fmaf(v.y, a, acc[q].y);
                acc[q].z = fmaf(v.z, a, acc[q].z);
                acc[q].w = fmaf(v.w, a, acc[q].w);
            }
        }
    }
#pragma unroll
    for (int o = 16; o; o >>= 1) {
        den.x += __shfl_xor_sync(0xffffffffu, den.x, o);
        den.y += __shfl_xor_sync(0xffffffffu, den.y, o);
        den.z += __shfl_xor_sync(0xffffffffu, den.z, o);
        den.w += __shfl_xor_sync(0xffffffffu, den.w, o);
    }

#pragma unroll
    for (int q = 0; q < Q; q++) {
        const float dh = hq[q] == 0 ? den.x : hq[q] == 1 ? den.y
                       : hq[q] == 2 ? den.z : den.w;
        const float inv = 1.f / (dh + 1e-16f);
        const float4 b4 = ((const float4*)bias)[lane + q * 32];
        float4 v;
        v.x = fmaxf(fmaf(acc[q].x, inv, b4.x), 0.f);
        v.y = fmaxf(fmaf(acc[q].y, inv, b4.y), 0.f);
        v.z = fmaxf(fmaf(acc[q].z, inv, b4.z), 0.f);
        v.w = fmaxf(fmaf(acc[q].w, inv, b4.w), 0.f);
        if (SPLIT_OUT) {
            const size_t off = (size_t)n * F + (size_t)(lane + q * 32) * 4;
            split2(Ohi, Olo, off, v.x, v.y);
            split2(Ohi, Olo, off + 2, v.z, v.w);
        } else {
            const int g = batch[n];
            red_add_v4(&g_POOL[g * OUT_DIM + lane * 4], v.x, v.y, v.z, v.w);
            if (lane == 0) atomicAdd(&g_CNT[g], 1.0f);
        }
    }
}

// ---------------- pool init + heads -----------------------------------------
__global__ void init_pool_kernel()
{
    int i = blockIdx.x * blockDim.x + threadIdx.x;
    if (i < N_GRAPHS * OUT_DIM) g_POOL[i] = 0.f;
    if (i < N_GRAPHS) g_CNT[i] = 0.f;
}

__global__ void head_kernel(const float* __restrict__ W_cls, const float* __restrict__ b_cls,
                            const float* __restrict__ W_conf, const float* __restrict__ b_conf,
                            float* __restrict__ out)
{
    int g = threadIdx.x;
    if (g >= N_GRAPHS) return;
    const float c = fmaxf(g_CNT[g], 1.0f);
    float l0 = b_cls[0], l1 = b_cls[1], cf = b_conf[0];
#pragma unroll 8
    for (int k = 0; k < OUT_DIM; k++) {
        const float m = g_POOL[g * OUT_DIM + k] / c;
        l0 = fmaf(m, W_cls[k * 2 + 0], l0);
        l1 = fmaf(m, W_cls[k * 2 + 1], l1);
        cf = fmaf(m, W_conf[k], cf);
    }
    out[g * 2 + 0] = l0;
    out[g * 2 + 1] = l1;
    out[N_GRAPHS * 2 + g] = 1.f / (1.f + expf(-cf));
}

// ---------------- launch ------------------------------------------------------
extern "C" void kernel_launch(void* const* d_in, const int* in_sizes, int n_in,
                              void* d_out, int out_size)
{
    const float* x     = (const float*)d_in[0];
    const int*   ei    = (const int*)d_in[1];
    const int*   batch = (const int*)d_in[2];
    const float* W_in = (const float*)d_in[3];
    const float* b_in = (const float*)d_in[4];
    const float* W1   = (const float*)d_in[5];
    const float* as1  = (const float*)d_in[6];
    const float* ad1  = (const float*)d_in[7];
    const float* b1   = (const float*)d_in[8];
    const float* W2   = (const float*)d_in[9];
    const float* as2  = (const float*)d_in[10];
    const float* ad2  = (const float*)d_in[11];
    const float* b2   = (const float*)d_in[12];
    const float* Wc   = (const float*)d_in[13];
    const float* bc   = (const float*)d_in[14];
    const float* Wf   = (const float*)d_in[15];
    const float* bf   = (const float*)d_in[16];
    float* out = (float*)d_out;

    const int* e_src = ei;
    const int* e_dst = ei + N_EDGES;

    float *AS, *AD;
    __nv_bfloat16 *HT1, *HT2, *Ahi, *Alo, *A2hi, *A2lo, *Bhi, *Blo;
    cudaGetSymbolAddress((void**)&HT1, g_HT1);
    cudaGetSymbolAddress((void**)&HT2, g_HT2);
    cudaGetSymbolAddress((void**)&AS,  g_AS);
    cudaGetSymbolAddress((void**)&AD,  g_AD);
    cudaGetSymbolAddress((void**)&Ahi,  g_Ahi);
    cudaGetSymbolAddress((void**)&Alo,  g_Alo);
    cudaGetSymbolAddress((void**)&A2hi, g_A2hi);
    cudaGetSymbolAddress((void**)&A2lo, g_A2lo);
    cudaGetSymbolAddress((void**)&Bhi, g_Bhi);
    cudaGetSymbolAddress((void**)&Blo, g_Blo);

    cudaFuncSetAttribute(gemm3t<KP1, true,  true,  true,  0 >, cudaFuncAttributeMaxDynamicSharedMemorySize, GEMM_SMEM);
    cudaFuncSetAttribute(gemm3t<HID, false, false, false, 64>, cudaFuncAttributeMaxDynamicSharedMemorySize, GEMM_SMEM);
    cudaFuncSetAttribute(gemm3t<HID, false, false, false, 32>, cudaFuncAttributeMaxDynamicSharedMemorySize, GEMM_SMEM);

    const dim3 blk(256);
    const int edge_blocks = (N_EDGES + 255) / 256;
    const int node_blocks = (N_NODES + 255) / 256;
    const int agg_blocks  = (int)(((size_t)N_NODES * 32 + 255) / 256);
    const int MTILES = M_PAD / 128;

    // launch order keeps gemm3t<KP1> at global launch #4 (empirical ncu slot)
    {
        const size_t tot = (size_t)M_PAD * (KP1 / 2);
        split_kernel<KP1, false><<<(unsigned)((tot + 255) / 256), blk>>>(x, N_NODES, IN_DIM, Ahi, Alo); // 1
    }
    wsplit_kernel<<<(HID * KP1 + 255) / 256, blk>>>(W_in, IN_DIM, HID, KP1, Bhi, Blo);                  // 2
    csr_deg_init<<<node_blocks, blk>>>();                                                               // 3
    {
        dim3 grid(MTILES, HID / 128);
        gemm3t<KP1, true, true, true, 0><<<grid, blk, GEMM_SMEM>>>(                                     // 4
            Ahi, Alo, Bhi, Blo, A2hi, A2lo, HID, b_in,
            nullptr, nullptr, nullptr, nullptr);
    }
    csr_count<<<edge_blocks, blk>>>(e_dst);                                                             // 5
    csr_scan<<<1, 1024>>>();                                                                            // 6
    csr_scatter<<<edge_blocks, blk>>>(e_src, e_dst);                                                    // 7
    // ===== GAT layer 1: HT1(bf16) = H0 @ W1 (+fused att1) =====
    wsplit_kernel<<<(HID * HID + 255) / 256, blk>>>(W1, HID, HID, HID, Bhi, Blo);
    {
        dim3 grid(MTILES, HID / 128);
        gemm3t<HID, false, false, false, 64><<<grid, blk, GEMM_SMEM>>>(
            A2hi, A2lo, Bhi, Blo, HT1, nullptr, HID, nullptr,
            as1, ad1, AS, AD);
    }
    agg_csr<64, 256, true><<<agg_blocks, blk>>>(HT1, AS, AD, b1, A2hi, A2lo, nullptr);
    // ===== GAT layer 2: HT2(bf16) = A2 @ W2 (+fused att2) =====
    wsplit_kernel<<<(OUT_DIM * HID + 255) / 256, blk>>>(W2, HID, OUT_DIM, HID, Bhi, Blo);
    {
        dim3 grid(MTILES, OUT_DIM / 128);
        gemm3t<HID, false, false, false, 32><<<grid, blk, GEMM_SMEM>>>(
            A2hi, A2lo, Bhi, Blo, HT2, nullptr, OUT_DIM, nullptr,
            as2, ad2, AS, AD);
    }
    init_pool_kernel<<<(N_GRAPHS * OUT_DIM + 255) / 256, blk>>>();
    agg_csr<32, 128, false><<<agg_blocks, blk>>>(HT2, AS, AD, b2, nullptr, nullptr, batch);
    // ===== heads =====
    head_kernel<<<1, 64>>>(Wc, bc, Wf, bf, out);
}